// round 15
// baseline (speedup 1.0000x reference)
#include <cuda_runtime.h>
#include <cuda_bf16.h>

// ---------------------------------------------------------------------------
// ViT block: LN1 -> per-head QKV -> attention(+residual) -> LN2(split-bf16)
//            -> MLP1 (bf16x3 tensor-core GEMM, gelu, split-bf16 out)
//            -> MLP2 (bf16x3 tensor-core GEMM + residual) 
// B=32, S=256, D=768, H=12, HD=64, MLP=3072.
// ---------------------------------------------------------------------------

#define B_   32
#define S_   256
#define D_   768
#define H_   12
#define HD_  64
#define MLP_ 3072
#define TOK_ (B_ * S_)   // 8192

// Scratch (device globals; no cudaMalloc allowed)
__device__ float g_h[(size_t)TOK_ * D_];            // ln1 output (fp32, for QKV)
__device__ float g_q[(size_t)TOK_ * D_];            // [B,H,S,HD]
__device__ float g_k[(size_t)TOK_ * D_];
__device__ float g_v[(size_t)TOK_ * D_];
__device__ float g_out1[(size_t)TOK_ * D_];         // ctx + x (residual stream)
__device__ __nv_bfloat16 g_hb[(size_t)TOK_ * 3 * D_];     // ln2 out, split [hi,lo,hi]
__device__ __nv_bfloat16 g_mb[(size_t)TOK_ * 3 * MLP_];   // gelu(mlp1), split [hi,lo,hi]
__device__ __nv_bfloat16 g_w1b[(size_t)MLP_ * 3 * D_];    // W1 split [hi,hi,lo]
__device__ __nv_bfloat16 g_w2b[(size_t)D_ * 3 * MLP_];    // W2 split [hi,hi,lo]

// ---------------------------------------------------------------------------
// PTX helpers
// ---------------------------------------------------------------------------
__device__ __forceinline__ void cpasync16(unsigned saddr, const void* g) {
    asm volatile("cp.async.cg.shared.global [%0], [%1], 16;\n" :: "r"(saddr), "l"(g));
}
__device__ __forceinline__ void cp_commit() { asm volatile("cp.async.commit_group;\n"); }
__device__ __forceinline__ void cp_wait1()  { asm volatile("cp.async.wait_group 1;\n"); }
__device__ __forceinline__ void cp_wait0()  { asm volatile("cp.async.wait_group 0;\n"); }

__device__ __forceinline__ void ldsm4(unsigned& r0, unsigned& r1, unsigned& r2, unsigned& r3,
                                      unsigned addr) {
    asm volatile("ldmatrix.sync.aligned.m8n8.x4.shared.b16 {%0,%1,%2,%3}, [%4];\n"
                 : "=r"(r0), "=r"(r1), "=r"(r2), "=r"(r3) : "r"(addr));
}
__device__ __forceinline__ void ldsm2(unsigned& r0, unsigned& r1, unsigned addr) {
    asm volatile("ldmatrix.sync.aligned.m8n8.x2.shared.b16 {%0,%1}, [%2];\n"
                 : "=r"(r0), "=r"(r1) : "r"(addr));
}
__device__ __forceinline__ void mma16816(float& c0, float& c1, float& c2, float& c3,
                                         unsigned a0, unsigned a1, unsigned a2, unsigned a3,
                                         unsigned b0, unsigned b1) {
    asm volatile(
        "mma.sync.aligned.m16n8k16.row.col.f32.bf16.bf16.f32 "
        "{%0,%1,%2,%3}, {%4,%5,%6,%7}, {%8,%9}, {%0,%1,%2,%3};\n"
        : "+f"(c0), "+f"(c1), "+f"(c2), "+f"(c3)
        : "r"(a0), "r"(a1), "r"(a2), "r"(a3), "r"(b0), "r"(b1));
}

__device__ __forceinline__ float gelu_exact(float v) {
    return 0.5f * v * (1.0f + erff(v * 0.70710678118654752f));
}
__device__ __forceinline__ void split_bf16(float v, __nv_bfloat16& h, __nv_bfloat16& l) {
    h = __float2bfloat16(v);
    l = __float2bfloat16(v - __bfloat162float(h));
}

// ---------------------------------------------------------------------------
// LayerNorm (fp32 out): one block per token, 256 threads
// ---------------------------------------------------------------------------
__global__ __launch_bounds__(256) void ln_kernel(
    const float* __restrict__ x, const float* __restrict__ g,
    const float* __restrict__ bet, float* __restrict__ o)
{
    __shared__ float red[16];
    int t = blockIdx.x, tid = threadIdx.x;
    const float* xr = x + (size_t)t * D_;
    float v0 = xr[tid], v1 = xr[tid + 256], v2 = xr[tid + 512];
    float s = v0 + v1 + v2, ss = v0 * v0 + v1 * v1 + v2 * v2;
#pragma unroll
    for (int off = 16; off; off >>= 1) {
        s  += __shfl_down_sync(0xffffffffu, s,  off);
        ss += __shfl_down_sync(0xffffffffu, ss, off);
    }
    if ((tid & 31) == 0) { red[tid >> 5] = s; red[8 + (tid >> 5)] = ss; }
    __syncthreads();
    float S = 0.f, SS = 0.f;
#pragma unroll
    for (int i = 0; i < 8; i++) { S += red[i]; SS += red[8 + i]; }
    float mu  = S * (1.0f / D_);
    float var = SS * (1.0f / D_) - mu * mu;
    float inv = rsqrtf(var + 1e-5f);
    float* orow = o + (size_t)t * D_;
    orow[tid]       = (v0 - mu) * inv * g[tid]       + bet[tid];
    orow[tid + 256] = (v1 - mu) * inv * g[tid + 256] + bet[tid + 256];
    orow[tid + 512] = (v2 - mu) * inv * g[tid + 512] + bet[tid + 512];
}

// LayerNorm with split-bf16 output in A-layout [hi | lo | hi], row length 3*D
__global__ __launch_bounds__(256) void ln_split_kernel(
    const float* __restrict__ x, const float* __restrict__ g,
    const float* __restrict__ bet, __nv_bfloat16* __restrict__ o)
{
    __shared__ float red[16];
    int t = blockIdx.x, tid = threadIdx.x;
    const float* xr = x + (size_t)t * D_;
    float v0 = xr[tid], v1 = xr[tid + 256], v2 = xr[tid + 512];
    float s = v0 + v1 + v2, ss = v0 * v0 + v1 * v1 + v2 * v2;
#pragma unroll
    for (int off = 16; off; off >>= 1) {
        s  += __shfl_down_sync(0xffffffffu, s,  off);
        ss += __shfl_down_sync(0xffffffffu, ss, off);
    }
    if ((tid & 31) == 0) { red[tid >> 5] = s; red[8 + (tid >> 5)] = ss; }
    __syncthreads();
    float S = 0.f, SS = 0.f;
#pragma unroll
    for (int i = 0; i < 8; i++) { S += red[i]; SS += red[8 + i]; }
    float mu  = S * (1.0f / D_);
    float var = SS * (1.0f / D_) - mu * mu;
    float inv = rsqrtf(var + 1e-5f);
    __nv_bfloat16* orow = o + (size_t)t * (3 * D_);
    float vv[3] = {v0, v1, v2};
#pragma unroll
    for (int p = 0; p < 3; p++) {
        int c = tid + p * 256;
        float y = (vv[p] - mu) * inv * g[c] + bet[c];
        __nv_bfloat16 h, l; split_bf16(y, h, l);
        orow[c] = h; orow[D_ + c] = l; orow[2 * D_ + c] = h;
    }
}

// Weight split to B-layout [hi | hi | lo], row length 3*K
__global__ __launch_bounds__(256) void wsplit_kernel(
    const float* __restrict__ W, __nv_bfloat16* __restrict__ Wb, int K, int total)
{
    int i = blockIdx.x * 256 + threadIdx.x;
    if (i >= total) return;
    int r = i / K, c = i % K;
    __nv_bfloat16 h, l; split_bf16(W[i], h, l);
    size_t rb = (size_t)r * 3 * K;
    Wb[rb + c] = h; Wb[rb + K + c] = h; Wb[rb + 2 * K + c] = l;
}

// ---------------------------------------------------------------------------
// Per-head QKV (fp32): grid (128 token-tiles, 12 heads, 3 matrices)
// ---------------------------------------------------------------------------
__global__ __launch_bounds__(256) void qkv_kernel(
    const float* __restrict__ Wq, const float* __restrict__ bq,
    const float* __restrict__ Wk, const float* __restrict__ bk,
    const float* __restrict__ Wv, const float* __restrict__ bv)
{
    __shared__ float As[64][65];
    __shared__ float Ws[64][65];
    int mt = blockIdx.x, head = blockIdx.y, which = blockIdx.z;
    const float* W    = (which == 0) ? Wq : (which == 1) ? Wk : Wv;
    const float* bias = (which == 0) ? bq : (which == 1) ? bk : bv;
    float* out        = (which == 0) ? g_q : (which == 1) ? g_k : g_v;

    int tid = threadIdx.x;
    int lr = tid >> 4, lc = (tid & 15) * 4;
#pragma unroll
    for (int p = 0; p < 4; p++) {
        int r = lr + p * 16;
        float4 a = *(const float4*)&g_h[(size_t)(mt * 64 + r) * D_ + head * 64 + lc];
        As[r][lc] = a.x; As[r][lc + 1] = a.y; As[r][lc + 2] = a.z; As[r][lc + 3] = a.w;
        float4 w = *(const float4*)&W[head * 4096 + r * 64 + lc];
        Ws[r][lc] = w.x; Ws[r][lc + 1] = w.y; Ws[r][lc + 2] = w.z; Ws[r][lc + 3] = w.w;
    }
    __syncthreads();

    int tx = tid & 15, ty = tid >> 4;
    float acc[4][4] = {};
#pragma unroll
    for (int d = 0; d < 64; d++) {
        float a[4], w[4];
#pragma unroll
        for (int i = 0; i < 4; i++) a[i] = As[ty * 4 + i][d];
#pragma unroll
        for (int j = 0; j < 4; j++) w[j] = Ws[tx * 4 + j][d];
#pragma unroll
        for (int i = 0; i < 4; i++)
#pragma unroll
            for (int j = 0; j < 4; j++)
                acc[i][j] = fmaf(a[i], w[j], acc[i][j]);
    }

    int t0 = mt * 64 + ty * 4;
#pragma unroll
    for (int i = 0; i < 4; i++) {
        int t = t0 + i;
        int bb = t / S_, ssi = t % S_;
        float* o = out + (((size_t)bb * H_ + head) * S_ + ssi) * HD_ + tx * 4;
        float4 r;
        r.x = acc[i][0] + bias[head * 64 + tx * 4 + 0];
        r.y = acc[i][1] + bias[head * 64 + tx * 4 + 1];
        r.z = acc[i][2] + bias[head * 64 + tx * 4 + 2];
        r.w = acc[i][3] + bias[head * 64 + tx * 4 + 3];
        *(float4*)o = r;
    }
}

// ---------------------------------------------------------------------------
// Attention (fp32): grid = B*H blocks, 256 threads (thread = query row)
// ---------------------------------------------------------------------------
__global__ __launch_bounds__(256) void attn_kernel(const float* __restrict__ x)
{
    extern __shared__ float sm[];
    float* Ks = sm;
    float* Vs = sm + S_ * HD_;
    int bh = blockIdx.x;
    int b = bh / H_, hh = bh % H_;
    size_t base = (size_t)bh * S_ * HD_;
    int tid = threadIdx.x;

    const float4* gk4 = (const float4*)(g_k + base);
    const float4* gv4 = (const float4*)(g_v + base);
    float4* K4 = (float4*)Ks;
    float4* V4 = (float4*)Vs;
#pragma unroll
    for (int i = 0; i < 16; i++) {
        K4[tid + i * 256] = gk4[tid + i * 256];
        V4[tid + i * 256] = gv4[tid + i * 256];
    }

    float q[64];
    {
        const float4* gq4 = (const float4*)(g_q + base + (size_t)tid * HD_);
#pragma unroll
        for (int c = 0; c < 16; c++) {
            float4 t4 = gq4[c];
            q[4 * c] = t4.x; q[4 * c + 1] = t4.y; q[4 * c + 2] = t4.z; q[4 * c + 3] = t4.w;
        }
    }
    __syncthreads();

    float mx = -1e30f, l = 0.f;
    float acc[64];
#pragma unroll
    for (int c = 0; c < 64; c++) acc[c] = 0.f;

    for (int j = 0; j < S_; j++) {
        const float4* kr = (const float4*)(Ks + j * HD_);
        float s0 = 0.f, s1 = 0.f, s2 = 0.f, s3 = 0.f;
#pragma unroll
        for (int c = 0; c < 16; c++) {
            float4 kv = kr[c];
            s0 = fmaf(q[4 * c],     kv.x, s0);
            s1 = fmaf(q[4 * c + 1], kv.y, s1);
            s2 = fmaf(q[4 * c + 2], kv.z, s2);
            s3 = fmaf(q[4 * c + 3], kv.w, s3);
        }
        float s = ((s0 + s1) + (s2 + s3)) * 0.125f;
        float mnew = fmaxf(mx, s);
        float corr = __expf(mx - mnew);
        float p    = __expf(s  - mnew);
        l = l * corr + p;
        const float4* vr = (const float4*)(Vs + j * HD_);
#pragma unroll
        for (int c = 0; c < 16; c++) {
            float4 vv = vr[c];
            acc[4 * c]     = fmaf(acc[4 * c],     corr, p * vv.x);
            acc[4 * c + 1] = fmaf(acc[4 * c + 1], corr, p * vv.y);
            acc[4 * c + 2] = fmaf(acc[4 * c + 2], corr, p * vv.z);
            acc[4 * c + 3] = fmaf(acc[4 * c + 3], corr, p * vv.w);
        }
        mx = mnew;
    }

    float inv = 1.f / l;
    size_t tok = (size_t)b * S_ + tid;
    float* o = g_out1 + tok * D_ + hh * HD_;
    const float* xr = x + tok * D_ + hh * HD_;
#pragma unroll
    for (int c = 0; c < 16; c++) {
        float4 xv = *(const float4*)(xr + 4 * c);
        float4 ov;
        ov.x = acc[4 * c]     * inv + xv.x;
        ov.y = acc[4 * c + 1] * inv + xv.y;
        ov.z = acc[4 * c + 2] * inv + xv.z;
        ov.w = acc[4 * c + 3] * inv + xv.w;
        *(float4*)(o + 4 * c) = ov;
    }
}

// ---------------------------------------------------------------------------
// bf16 tensor-core GEMM:  C[M,N] = A[M,K3] @ Bt[N,K3]^T  (both K-major bf16)
// 128x128 block tile, K-tile 32, double-buffered cp.async, 8 warps (2x4),
// warp tile 64x32, mma.m16n8k16.  Epilogue:
//   MODE 0 (MLP1): gelu(acc+bias) -> split-bf16 out Cb rows of 3N [hi|lo|hi]
//   MODE 1 (MLP2): acc+bias+res   -> fp32 out Cf
// ---------------------------------------------------------------------------
#define SMPAD 40                      // 32 cols + 8 pad (bf16 elems)
#define BUFB  (128 * SMPAD * 2)       // bytes per buffer

template <int K3, int MODE>
__global__ __launch_bounds__(256) void bgemm_kernel(
    const __nv_bfloat16* __restrict__ A, const __nv_bfloat16* __restrict__ Bt,
    const float* __restrict__ bias, const float* __restrict__ res,
    float* __restrict__ Cf, __nv_bfloat16* __restrict__ Cb, int N)
{
    __shared__ __nv_bfloat16 smA[2 * 128 * SMPAD];
    __shared__ __nv_bfloat16 smB[2 * 128 * SMPAD];

    const int tid = threadIdx.x;
    const int lane = tid & 31, wid = tid >> 5;
    const int m0 = blockIdx.y * 128, n0 = blockIdx.x * 128;
    const int wm = (wid >> 2) * 64, wn = (wid & 3) * 32;

    // loader mapping: row = tid>>1 (0..127), col base = (tid&1)*16
    const int ldr = tid >> 1;
    const int ldc = (tid & 1) * 16;
    const __nv_bfloat16* Ag = A  + (size_t)(m0 + ldr) * K3 + ldc;
    const __nv_bfloat16* Bg = Bt + (size_t)(n0 + ldr) * K3 + ldc;
    const unsigned aBase = (unsigned)__cvta_generic_to_shared(smA);
    const unsigned bBase = (unsigned)__cvta_generic_to_shared(smB);
    const unsigned sAthr = aBase + (ldr * SMPAD + ldc) * 2;
    const unsigned sBthr = bBase + (ldr * SMPAD + ldc) * 2;

    // ldmatrix lane mapping
    const int aRow = wm + (lane & 15);          // + mi*16
    const int aCol = (lane >> 4) * 8;           // + kh*16
    const int bRow = wn + (lane & 7);           // + ni*8
    const int bCol = ((lane >> 3) & 1) * 8;     // + kh*16

    float acc[4][4][4];
#pragma unroll
    for (int mi = 0; mi < 4; mi++)
#pragma unroll
        for (int ni = 0; ni < 4; ni++)
#pragma unroll
            for (int r = 0; r < 4; r++) acc[mi][ni][r] = 0.f;

    constexpr int NK = K3 / 32;

#define LOADSTAGE(buf, kt)                                         \
    do {                                                           \
        cpasync16(sAthr + (buf) * BUFB,      Ag + (kt) * 32);      \
        cpasync16(sAthr + (buf) * BUFB + 16, Ag + (kt) * 32 + 8);  \
        cpasync16(sBthr + (buf) * BUFB,      Bg + (kt) * 32);      \
        cpasync16(sBthr + (buf) * BUFB + 16, Bg + (kt) * 32 + 8);  \
        cp_commit();                                               \
    } while (0)

    LOADSTAGE(0, 0);
    LOADSTAGE(1, 1);

    for (int kt = 0; kt < NK; kt++) {
        const int buf = kt & 1;
        if (kt + 1 == NK) cp_wait0(); else cp_wait1();
        __syncthreads();

        const unsigned bufOff = buf * BUFB;
#pragma unroll
        for (int kh = 0; kh < 2; kh++) {
            unsigned a[4][4], b[4][2];
#pragma unroll
            for (int mi = 0; mi < 4; mi++) {
                unsigned addr = aBase + bufOff +
                    ((aRow + mi * 16) * SMPAD + aCol + kh * 16) * 2;
                ldsm4(a[mi][0], a[mi][1], a[mi][2], a[mi][3], addr);
            }
#pragma unroll
            for (int ni = 0; ni < 4; ni++) {
                unsigned addr = bBase + bufOff +
                    ((bRow + ni * 8) * SMPAD + bCol + kh * 16) * 2;
                ldsm2(b[ni][0], b[ni][1], addr);
            }
#pragma unroll
            for (int mi = 0; mi < 4; mi++)
#pragma unroll
                for (int ni = 0; ni < 4; ni++)
                    mma16816(acc[mi][ni][0], acc[mi][ni][1],
                             acc[mi][ni][2], acc[mi][ni][3],
                             a[mi][0], a[mi][1], a[mi][2], a[mi][3],
                             b[ni][0], b[ni][1]);
        }
        __syncthreads();
        if (kt + 2 < NK) LOADSTAGE(buf, kt + 2);
    }
#undef LOADSTAGE

    // epilogue
    const int g = lane >> 2, t4 = lane & 3;
#pragma unroll
    for (int mi = 0; mi < 4; mi++) {
#pragma unroll
        for (int ni = 0; ni < 4; ni++) {
            int row0 = m0 + wm + mi * 16 + g;
            int col  = n0 + wn + ni * 8 + t4 * 2;
            float b0 = __ldg(&bias[col]), b1 = __ldg(&bias[col + 1]);
#pragma unroll
            for (int half = 0; half < 2; half++) {
                int r = row0 + half * 8;
                float v0 = acc[mi][ni][half * 2 + 0] + b0;
                float v1 = acc[mi][ni][half * 2 + 1] + b1;
                if (MODE == 0) {
                    v0 = gelu_exact(v0); v1 = gelu_exact(v1);
                    __nv_bfloat16 h0, l0, h1, l1;
                    split_bf16(v0, h0, l0); split_bf16(v1, h1, l1);
                    __nv_bfloat162 hp; hp.x = h0; hp.y = h1;
                    __nv_bfloat162 lp; lp.x = l0; lp.y = l1;
                    size_t base = (size_t)r * (3 * N) + col;
                    *(__nv_bfloat162*)&Cb[base]         = hp;
                    *(__nv_bfloat162*)&Cb[base + N]     = lp;
                    *(__nv_bfloat162*)&Cb[base + 2 * N] = hp;
                } else {
                    size_t o = (size_t)r * N + col;
                    float2 rr = *(const float2*)&res[o];
                    float2 ov; ov.x = v0 + rr.x; ov.y = v1 + rr.y;
                    *(float2*)&Cf[o] = ov;
                }
            }
        }
    }
}

// ---------------------------------------------------------------------------
// Launch
// ---------------------------------------------------------------------------
extern "C" void kernel_launch(void* const* d_in, const int* in_sizes, int n_in,
                              void* d_out, int out_size)
{
    const float* x     = (const float*)d_in[0];
    const float* g1    = (const float*)d_in[1];
    const float* beta1 = (const float*)d_in[2];
    const float* Wq    = (const float*)d_in[3];
    const float* bq    = (const float*)d_in[4];
    const float* Wk    = (const float*)d_in[5];
    const float* bk    = (const float*)d_in[6];
    const float* Wv    = (const float*)d_in[7];
    const float* bv    = (const float*)d_in[8];
    const float* g2    = (const float*)d_in[9];
    const float* beta2 = (const float*)d_in[10];
    const float* W1    = (const float*)d_in[11];
    const float* bm1   = (const float*)d_in[12];
    const float* W2    = (const float*)d_in[13];
    const float* bm2   = (const float*)d_in[14];
    float* out = (float*)d_out;

    float *p_h, *p_out1;
    __nv_bfloat16 *p_hb, *p_mb, *p_w1b, *p_w2b;
    cudaGetSymbolAddress((void**)&p_h,    g_h);
    cudaGetSymbolAddress((void**)&p_out1, g_out1);
    cudaGetSymbolAddress((void**)&p_hb,   g_hb);
    cudaGetSymbolAddress((void**)&p_mb,   g_mb);
    cudaGetSymbolAddress((void**)&p_w1b,  g_w1b);
    cudaGetSymbolAddress((void**)&p_w2b,  g_w2b);

    cudaFuncSetAttribute(attn_kernel,
                         cudaFuncAttributeMaxDynamicSharedMemorySize, 131072);

    // LN1 -> g_h (fp32)
    ln_kernel<<<TOK_, 256>>>(x, g1, beta1, p_h);
    // weight splits (independent of activations)
    wsplit_kernel<<<(MLP_ * D_ + 255) / 256, 256>>>(W1, p_w1b, D_,  MLP_ * D_);
    wsplit_kernel<<<(D_ * MLP_ + 255) / 256, 256>>>(W2, p_w2b, MLP_, D_ * MLP_);
    // per-head Q/K/V
    qkv_kernel<<<dim3(128, H_, 3), 256>>>(Wq, bq, Wk, bk, Wv, bv);
    // attention + residual -> g_out1
    attn_kernel<<<B_ * H_, 256, 131072>>>(x);
    // LN2 -> g_hb (split bf16, K3 = 2304)
    ln_split_kernel<<<TOK_, 256>>>(p_out1, g2, beta2, p_hb);
    // MLP1: gelu(h2 @ W1^T + bm1) -> g_mb (split bf16, K3 = 9216)
    bgemm_kernel<3 * D_, 0><<<dim3(MLP_ / 128, TOK_ / 128), 256>>>(
        p_hb, p_w1b, bm1, nullptr, nullptr, p_mb, MLP_);
    // MLP2: m @ W2^T + bm2 + out1 -> d_out (fp32)
    bgemm_kernel<3 * MLP_, 1><<<dim3(D_ / 128, TOK_ / 128), 256>>>(
        p_mb, p_w2b, bm2, p_out1, out, nullptr, D_);
}

// round 17
// speedup vs baseline: 1.1288x; 1.1288x over previous
#include <cuda_runtime.h>
#include <cuda_bf16.h>
#include <cstdint>

// ---------------------------------------------------------------------------
// ViT block: LN1 -> per-head QKV -> attention(+residual) -> LN2(split-bf16)
//            -> MLP1 (bf16x3 mma.sync GEMM, gelu, split-bf16 out)
//            -> MLP2 (bf16x3 mma.sync GEMM + residual)
// B=32, S=256, D=768, H=12, HD=64, MLP=3072.
// NOTE: tcgen05 is unavailable (harness PTX target is compute_103, not 103a);
// the tensor path is legacy mma.sync.m16n8k16.bf16.
// ---------------------------------------------------------------------------

#define B_   32
#define S_   256
#define D_   768
#define H_   12
#define HD_  64
#define MLP_ 3072
#define TOK_ (B_ * S_)   // 8192

// Scratch (device globals; no cudaMalloc allowed)
__device__ float g_h[(size_t)TOK_ * D_];            // ln1 output (fp32, for QKV)
__device__ float g_q[(size_t)TOK_ * D_];            // [B,H,S,HD]
__device__ float g_k[(size_t)TOK_ * D_];
__device__ float g_v[(size_t)TOK_ * D_];
__device__ float g_out1[(size_t)TOK_ * D_];         // ctx + x (residual stream)
__device__ __nv_bfloat16 g_hb[(size_t)TOK_ * 3 * D_];     // ln2 out, split [hi,lo,hi]
__device__ __nv_bfloat16 g_mb[(size_t)TOK_ * 3 * MLP_];   // gelu(mlp1), split [hi,lo,hi]
__device__ __nv_bfloat16 g_w1b[(size_t)MLP_ * 3 * D_];    // W1 split [hi,hi,lo]
__device__ __nv_bfloat16 g_w2b[(size_t)D_ * 3 * MLP_];    // W2 split [hi,hi,lo]

// ---------------------------------------------------------------------------
// PTX helpers
// ---------------------------------------------------------------------------
__device__ __forceinline__ void cpasync16(unsigned saddr, const void* g) {
    asm volatile("cp.async.cg.shared.global [%0], [%1], 16;\n" :: "r"(saddr), "l"(g));
}
__device__ __forceinline__ void cp_commit() { asm volatile("cp.async.commit_group;\n"); }
__device__ __forceinline__ void cp_wait2()  { asm volatile("cp.async.wait_group 2;\n"); }

__device__ __forceinline__ void ldsm4(unsigned& r0, unsigned& r1, unsigned& r2, unsigned& r3,
                                      unsigned addr) {
    asm volatile("ldmatrix.sync.aligned.m8n8.x4.shared.b16 {%0,%1,%2,%3}, [%4];\n"
                 : "=r"(r0), "=r"(r1), "=r"(r2), "=r"(r3) : "r"(addr));
}
__device__ __forceinline__ void ldsm2(unsigned& r0, unsigned& r1, unsigned addr) {
    asm volatile("ldmatrix.sync.aligned.m8n8.x2.shared.b16 {%0,%1}, [%2];\n"
                 : "=r"(r0), "=r"(r1) : "r"(addr));
}
__device__ __forceinline__ void mma16816(float& c0, float& c1, float& c2, float& c3,
                                         unsigned a0, unsigned a1, unsigned a2, unsigned a3,
                                         unsigned b0, unsigned b1) {
    asm volatile(
        "mma.sync.aligned.m16n8k16.row.col.f32.bf16.bf16.f32 "
        "{%0,%1,%2,%3}, {%4,%5,%6,%7}, {%8,%9}, {%0,%1,%2,%3};\n"
        : "+f"(c0), "+f"(c1), "+f"(c2), "+f"(c3)
        : "r"(a0), "r"(a1), "r"(a2), "r"(a3), "r"(b0), "r"(b1));
}

__device__ __forceinline__ float gelu_exact(float v) {
    return 0.5f * v * (1.0f + erff(v * 0.70710678118654752f));
}
__device__ __forceinline__ void split_bf16(float v, __nv_bfloat16& h, __nv_bfloat16& l) {
    h = __float2bfloat16(v);
    l = __float2bfloat16(v - __bfloat162float(h));
}

// ---------------------------------------------------------------------------
// LayerNorm (fp32 out)
// ---------------------------------------------------------------------------
__global__ __launch_bounds__(256) void ln_kernel(
    const float* __restrict__ x, const float* __restrict__ g,
    const float* __restrict__ bet, float* __restrict__ o)
{
    __shared__ float red[16];
    int t = blockIdx.x, tid = threadIdx.x;
    const float* xr = x + (size_t)t * D_;
    float v0 = xr[tid], v1 = xr[tid + 256], v2 = xr[tid + 512];
    float s = v0 + v1 + v2, ss = v0 * v0 + v1 * v1 + v2 * v2;
#pragma unroll
    for (int off = 16; off; off >>= 1) {
        s  += __shfl_down_sync(0xffffffffu, s,  off);
        ss += __shfl_down_sync(0xffffffffu, ss, off);
    }
    if ((tid & 31) == 0) { red[tid >> 5] = s; red[8 + (tid >> 5)] = ss; }
    __syncthreads();
    float S = 0.f, SS = 0.f;
#pragma unroll
    for (int i = 0; i < 8; i++) { S += red[i]; SS += red[8 + i]; }
    float mu  = S * (1.0f / D_);
    float var = SS * (1.0f / D_) - mu * mu;
    float inv = rsqrtf(var + 1e-5f);
    float* orow = o + (size_t)t * D_;
    orow[tid]       = (v0 - mu) * inv * g[tid]       + bet[tid];
    orow[tid + 256] = (v1 - mu) * inv * g[tid + 256] + bet[tid + 256];
    orow[tid + 512] = (v2 - mu) * inv * g[tid + 512] + bet[tid + 512];
}

// LayerNorm with split-bf16 output [hi | lo | hi], row length 3*D
__global__ __launch_bounds__(256) void ln_split_kernel(
    const float* __restrict__ x, const float* __restrict__ g,
    const float* __restrict__ bet, __nv_bfloat16* __restrict__ o)
{
    __shared__ float red[16];
    int t = blockIdx.x, tid = threadIdx.x;
    const float* xr = x + (size_t)t * D_;
    float v0 = xr[tid], v1 = xr[tid + 256], v2 = xr[tid + 512];
    float s = v0 + v1 + v2, ss = v0 * v0 + v1 * v1 + v2 * v2;
#pragma unroll
    for (int off = 16; off; off >>= 1) {
        s  += __shfl_down_sync(0xffffffffu, s,  off);
        ss += __shfl_down_sync(0xffffffffu, ss, off);
    }
    if ((tid & 31) == 0) { red[tid >> 5] = s; red[8 + (tid >> 5)] = ss; }
    __syncthreads();
    float S = 0.f, SS = 0.f;
#pragma unroll
    for (int i = 0; i < 8; i++) { S += red[i]; SS += red[8 + i]; }
    float mu  = S * (1.0f / D_);
    float var = SS * (1.0f / D_) - mu * mu;
    float inv = rsqrtf(var + 1e-5f);
    __nv_bfloat16* orow = o + (size_t)t * (3 * D_);
    float vv[3] = {v0, v1, v2};
#pragma unroll
    for (int p = 0; p < 3; p++) {
        int c = tid + p * 256;
        float y = (vv[p] - mu) * inv * g[c] + bet[c];
        __nv_bfloat16 h, l; split_bf16(y, h, l);
        orow[c] = h; orow[D_ + c] = l; orow[2 * D_ + c] = h;
    }
}

// Weight split to B-layout [hi | hi | lo], row length 3*K
__global__ __launch_bounds__(256) void wsplit_kernel(
    const float* __restrict__ W, __nv_bfloat16* __restrict__ Wb, int K, int total)
{
    int i = blockIdx.x * 256 + threadIdx.x;
    if (i >= total) return;
    int r = i / K, c = i % K;
    __nv_bfloat16 h, l; split_bf16(W[i], h, l);
    size_t rb = (size_t)r * 3 * K;
    Wb[rb + c] = h; Wb[rb + K + c] = h; Wb[rb + 2 * K + c] = l;
}

// ---------------------------------------------------------------------------
// Per-head QKV (fp32)
// ---------------------------------------------------------------------------
__global__ __launch_bounds__(256) void qkv_kernel(
    const float* __restrict__ Wq, const float* __restrict__ bq,
    const float* __restrict__ Wk, const float* __restrict__ bk,
    const float* __restrict__ Wv, const float* __restrict__ bv)
{
    __shared__ float As[64][65];
    __shared__ float Ws[64][65];
    int mt = blockIdx.x, head = blockIdx.y, which = blockIdx.z;
    const float* W    = (which == 0) ? Wq : (which == 1) ? Wk : Wv;
    const float* bias = (which == 0) ? bq : (which == 1) ? bk : bv;
    float* out        = (which == 0) ? g_q : (which == 1) ? g_k : g_v;

    int tid = threadIdx.x;
    int lr = tid >> 4, lc = (tid & 15) * 4;
#pragma unroll
    for (int p = 0; p < 4; p++) {
        int r = lr + p * 16;
        float4 a = *(const float4*)&g_h[(size_t)(mt * 64 + r) * D_ + head * 64 + lc];
        As[r][lc] = a.x; As[r][lc + 1] = a.y; As[r][lc + 2] = a.z; As[r][lc + 3] = a.w;
        float4 w = *(const float4*)&W[head * 4096 + r * 64 + lc];
        Ws[r][lc] = w.x; Ws[r][lc + 1] = w.y; Ws[r][lc + 2] = w.z; Ws[r][lc + 3] = w.w;
    }
    __syncthreads();

    int tx = tid & 15, ty = tid >> 4;
    float acc[4][4] = {};
#pragma unroll
    for (int d = 0; d < 64; d++) {
        float a[4], w[4];
#pragma unroll
        for (int i = 0; i < 4; i++) a[i] = As[ty * 4 + i][d];
#pragma unroll
        for (int j = 0; j < 4; j++) w[j] = Ws[tx * 4 + j][d];
#pragma unroll
        for (int i = 0; i < 4; i++)
#pragma unroll
            for (int j = 0; j < 4; j++)
                acc[i][j] = fmaf(a[i], w[j], acc[i][j]);
    }

    int t0 = mt * 64 + ty * 4;
#pragma unroll
    for (int i = 0; i < 4; i++) {
        int t = t0 + i;
        int bb = t / S_, ssi = t % S_;
        float* o = out + (((size_t)bb * H_ + head) * S_ + ssi) * HD_ + tx * 4;
        float4 r;
        r.x = acc[i][0] + bias[head * 64 + tx * 4 + 0];
        r.y = acc[i][1] + bias[head * 64 + tx * 4 + 1];
        r.z = acc[i][2] + bias[head * 64 + tx * 4 + 2];
        r.w = acc[i][3] + bias[head * 64 + tx * 4 + 3];
        *(float4*)o = r;
    }
}

// ---------------------------------------------------------------------------
// Attention (fp32): grid = B*H blocks, 256 threads (thread = query row)
// ---------------------------------------------------------------------------
__global__ __launch_bounds__(256) void attn_kernel(const float* __restrict__ x)
{
    extern __shared__ float sm[];
    float* Ks = sm;
    float* Vs = sm + S_ * HD_;
    int bh = blockIdx.x;
    int b = bh / H_, hh = bh % H_;
    size_t base = (size_t)bh * S_ * HD_;
    int tid = threadIdx.x;

    const float4* gk4 = (const float4*)(g_k + base);
    const float4* gv4 = (const float4*)(g_v + base);
    float4* K4 = (float4*)Ks;
    float4* V4 = (float4*)Vs;
#pragma unroll
    for (int i = 0; i < 16; i++) {
        K4[tid + i * 256] = gk4[tid + i * 256];
        V4[tid + i * 256] = gv4[tid + i * 256];
    }

    float q[64];
    {
        const float4* gq4 = (const float4*)(g_q + base + (size_t)tid * HD_);
#pragma unroll
        for (int c = 0; c < 16; c++) {
            float4 t4 = gq4[c];
            q[4 * c] = t4.x; q[4 * c + 1] = t4.y; q[4 * c + 2] = t4.z; q[4 * c + 3] = t4.w;
        }
    }
    __syncthreads();

    float mx = -1e30f, l = 0.f;
    float acc[64];
#pragma unroll
    for (int c = 0; c < 64; c++) acc[c] = 0.f;

    for (int j = 0; j < S_; j++) {
        const float4* kr = (const float4*)(Ks + j * HD_);
        float s0 = 0.f, s1 = 0.f, s2 = 0.f, s3 = 0.f;
#pragma unroll
        for (int c = 0; c < 16; c++) {
            float4 kv = kr[c];
            s0 = fmaf(q[4 * c],     kv.x, s0);
            s1 = fmaf(q[4 * c + 1], kv.y, s1);
            s2 = fmaf(q[4 * c + 2], kv.z, s2);
            s3 = fmaf(q[4 * c + 3], kv.w, s3);
        }
        float s = ((s0 + s1) + (s2 + s3)) * 0.125f;
        float mnew = fmaxf(mx, s);
        float corr = __expf(mx - mnew);
        float p    = __expf(s  - mnew);
        l = l * corr + p;
        const float4* vr = (const float4*)(Vs + j * HD_);
#pragma unroll
        for (int c = 0; c < 16; c++) {
            float4 vv = vr[c];
            acc[4 * c]     = fmaf(acc[4 * c],     corr, p * vv.x);
            acc[4 * c + 1] = fmaf(acc[4 * c + 1], corr, p * vv.y);
            acc[4 * c + 2] = fmaf(acc[4 * c + 2], corr, p * vv.z);
            acc[4 * c + 3] = fmaf(acc[4 * c + 3], corr, p * vv.w);
        }
        mx = mnew;
    }

    float inv = 1.f / l;
    size_t tok = (size_t)b * S_ + tid;
    float* o = g_out1 + tok * D_ + hh * HD_;
    const float* xr = x + tok * D_ + hh * HD_;
#pragma unroll
    for (int c = 0; c < 16; c++) {
        float4 xv = *(const float4*)(xr + 4 * c);
        float4 ov;
        ov.x = acc[4 * c]     * inv + xv.x;
        ov.y = acc[4 * c + 1] * inv + xv.y;
        ov.z = acc[4 * c + 2] * inv + xv.z;
        ov.w = acc[4 * c + 3] * inv + xv.w;
        *(float4*)(o + 4 * c) = ov;
    }
}

// ---------------------------------------------------------------------------
// bf16 tensor-core GEMM:  C[M,N] = A[M,K3] @ Bt[N,K3]^T  (both K-major bf16)
// 128x128 block tile, K-tile 32, 4-stage cp.async pipeline (circular buffers,
// ONE __syncthreads per K-iter, empty commit groups in the tail so that
// wait_group 2 is uniform).  8 warps (2x4), warp tile 64x32, mma.m16n8k16.
// Epilogue:
//   MODE 0 (MLP1): gelu(acc+bias) -> split-bf16 out Cb rows of 3N [hi|lo|hi]
//   MODE 1 (MLP2): acc+bias+res   -> fp32 out Cf
// ---------------------------------------------------------------------------
#define SMPAD  40                      // 32 cols + 8 pad (bf16 elems)
#define STAGEB (2 * 128 * SMPAD * 2)   // A+B bytes per stage = 20480
#define NSTG   4
#define GSMEM_ (NSTG * STAGEB)         // 81920 bytes dynamic smem

template <int K3, int MODE>
__global__ __launch_bounds__(256, 2) void bgemm_kernel(
    const __nv_bfloat16* __restrict__ A, const __nv_bfloat16* __restrict__ Bt,
    const float* __restrict__ bias, const float* __restrict__ res,
    float* __restrict__ Cf, __nv_bfloat16* __restrict__ Cb, int N)
{
    extern __shared__ __align__(16) __nv_bfloat16 dynsm[];

    const int tid = threadIdx.x;
    const int lane = tid & 31, wid = tid >> 5;
    const int m0 = blockIdx.y * 128, n0 = blockIdx.x * 128;
    const int wm = (wid >> 2) * 64, wn = (wid & 3) * 32;

    // loader mapping: row = tid>>1 (0..127), col base = (tid&1)*16 elems
    const int ldr = tid >> 1;
    const int ldc = (tid & 1) * 16;
    const __nv_bfloat16* Ag = A  + (size_t)(m0 + ldr) * K3 + ldc;
    const __nv_bfloat16* Bg = Bt + (size_t)(n0 + ldr) * K3 + ldc;
    const unsigned smBase = (unsigned)__cvta_generic_to_shared(dynsm);
    // within a stage: A at 0, B at 128*SMPAD*2 bytes
    const unsigned sAthr = smBase + (ldr * SMPAD + ldc) * 2;
    const unsigned sBthr = smBase + 128 * SMPAD * 2 + (ldr * SMPAD + ldc) * 2;

    // ldmatrix lane mapping
    const int aRow = wm + (lane & 15);          // + mi*16
    const int aCol = (lane >> 4) * 8;           // + kh*16
    const int bRow = wn + (lane & 7);           // + ni*8
    const int bCol = ((lane >> 3) & 1) * 8;     // + kh*16

    float acc[4][4][4];
#pragma unroll
    for (int mi = 0; mi < 4; mi++)
#pragma unroll
        for (int ni = 0; ni < 4; ni++)
#pragma unroll
            for (int r = 0; r < 4; r++) acc[mi][ni][r] = 0.f;

    constexpr int NK = K3 / 32;

#define LOADSTAGE(stg, kt)                                                  \
    do {                                                                    \
        unsigned off = (stg) * STAGEB;                                      \
        cpasync16(sAthr + off,      Ag + (kt) * 32);                        \
        cpasync16(sAthr + off + 16, Ag + (kt) * 32 + 8);                    \
        cpasync16(sBthr + off,      Bg + (kt) * 32);                        \
        cpasync16(sBthr + off + 16, Bg + (kt) * 32 + 8);                    \
        cp_commit();                                                        \
    } while (0)

    // prologue: fill 3 stages
    LOADSTAGE(0, 0);
    LOADSTAGE(1, 1);
    LOADSTAGE(2, 2);

    for (int kt = 0; kt < NK; kt++) {
        const int stg = kt & (NSTG - 1);
        cp_wait2();            // stage kt complete (2 younger groups pending)
        __syncthreads();       // also protects stage (kt+3)&3 from overwrite

        const unsigned bufOff = stg * STAGEB;
#pragma unroll
        for (int kh = 0; kh < 2; kh++) {
            unsigned a[4][4], b[4][2];
#pragma unroll
            for (int mi = 0; mi < 4; mi++) {
                unsigned addr = smBase + bufOff +
                    ((aRow + mi * 16) * SMPAD + aCol + kh * 16) * 2;
                ldsm4(a[mi][0], a[mi][1], a[mi][2], a[mi][3], addr);
            }
#pragma unroll
            for (int ni = 0; ni < 4; ni++) {
                unsigned addr = smBase + 128 * SMPAD * 2 + bufOff +
                    ((bRow + ni * 8) * SMPAD + bCol + kh * 16) * 2;
                ldsm2(b[ni][0], b[ni][1], addr);
            }
#pragma unroll
            for (int mi = 0; mi < 4; mi++)
#pragma unroll
                for (int ni = 0; ni < 4; ni++)
                    mma16816(acc[mi][ni][0], acc[mi][ni][1],
                             acc[mi][ni][2], acc[mi][ni][3],
                             a[mi][0], a[mi][1], a[mi][2], a[mi][3],
                             b[ni][0], b[ni][1]);
        }

        // issue next stage (or an empty group to keep the count uniform)
        if (kt + 3 < NK) {
            LOADSTAGE((kt + 3) & (NSTG - 1), kt + 3);
        } else {
            cp_commit();
        }
    }
#undef LOADSTAGE

    // epilogue
    const int g = lane >> 2, t4 = lane & 3;
#pragma unroll
    for (int mi = 0; mi < 4; mi++) {
#pragma unroll
        for (int ni = 0; ni < 4; ni++) {
            int row0 = m0 + wm + mi * 16 + g;
            int col  = n0 + wn + ni * 8 + t4 * 2;
            float b0 = __ldg(&bias[col]), b1 = __ldg(&bias[col + 1]);
#pragma unroll
            for (int half = 0; half < 2; half++) {
                int r = row0 + half * 8;
                float v0 = acc[mi][ni][half * 2 + 0] + b0;
                float v1 = acc[mi][ni][half * 2 + 1] + b1;
                if (MODE == 0) {
                    v0 = gelu_exact(v0); v1 = gelu_exact(v1);
                    __nv_bfloat16 h0, l0, h1, l1;
                    split_bf16(v0, h0, l0); split_bf16(v1, h1, l1);
                    __nv_bfloat162 hp; hp.x = h0; hp.y = h1;
                    __nv_bfloat162 lp; lp.x = l0; lp.y = l1;
                    size_t base = (size_t)r * (3 * (size_t)N) + col;
                    *(__nv_bfloat162*)&Cb[base]         = hp;
                    *(__nv_bfloat162*)&Cb[base + N]     = lp;
                    *(__nv_bfloat162*)&Cb[base + 2 * N] = hp;
                } else {
                    size_t o = (size_t)r * N + col;
                    float2 rr = *(const float2*)&res[o];
                    float2 ov; ov.x = v0 + rr.x; ov.y = v1 + rr.y;
                    *(float2*)&Cf[o] = ov;
                }
            }
        }
    }
}

// ---------------------------------------------------------------------------
// Launch
// ---------------------------------------------------------------------------
extern "C" void kernel_launch(void* const* d_in, const int* in_sizes, int n_in,
                              void* d_out, int out_size)
{
    const float* x     = (const float*)d_in[0];
    const float* g1    = (const float*)d_in[1];
    const float* beta1 = (const float*)d_in[2];
    const float* Wq    = (const float*)d_in[3];
    const float* bq    = (const float*)d_in[4];
    const float* Wk    = (const float*)d_in[5];
    const float* bk    = (const float*)d_in[6];
    const float* Wv    = (const float*)d_in[7];
    const float* bv    = (const float*)d_in[8];
    const float* g2    = (const float*)d_in[9];
    const float* beta2 = (const float*)d_in[10];
    const float* W1    = (const float*)d_in[11];
    const float* bm1   = (const float*)d_in[12];
    const float* W2    = (const float*)d_in[13];
    const float* bm2   = (const float*)d_in[14];
    float* out = (float*)d_out;

    float *p_h, *p_out1;
    __nv_bfloat16 *p_hb, *p_mb, *p_w1b, *p_w2b;
    cudaGetSymbolAddress((void**)&p_h,    g_h);
    cudaGetSymbolAddress((void**)&p_out1, g_out1);
    cudaGetSymbolAddress((void**)&p_hb,   g_hb);
    cudaGetSymbolAddress((void**)&p_mb,   g_mb);
    cudaGetSymbolAddress((void**)&p_w1b,  g_w1b);
    cudaGetSymbolAddress((void**)&p_w2b,  g_w2b);

    cudaFuncSetAttribute(attn_kernel,
                         cudaFuncAttributeMaxDynamicSharedMemorySize, 131072);
    cudaFuncSetAttribute(bgemm_kernel<3 * D_, 0>,
                         cudaFuncAttributeMaxDynamicSharedMemorySize, GSMEM_);
    cudaFuncSetAttribute(bgemm_kernel<3 * MLP_, 1>,
                         cudaFuncAttributeMaxDynamicSharedMemorySize, GSMEM_);

    // LN1 -> g_h (fp32)
    ln_kernel<<<TOK_, 256>>>(x, g1, beta1, p_h);
    // weight splits (independent of activations)
    wsplit_kernel<<<(MLP_ * D_ + 255) / 256, 256>>>(W1, p_w1b, D_,  MLP_ * D_);
    wsplit_kernel<<<(D_ * MLP_ + 255) / 256, 256>>>(W2, p_w2b, MLP_, D_ * MLP_);
    // per-head Q/K/V
    qkv_kernel<<<dim3(128, H_, 3), 256>>>(Wq, bq, Wk, bk, Wv, bv);
    // attention + residual -> g_out1
    attn_kernel<<<B_ * H_, 256, 131072>>>(x);
    // LN2 -> g_hb (split bf16, K3 = 2304)
    ln_split_kernel<<<TOK_, 256>>>(p_out1, g2, beta2, p_hb);
    // MLP1: gelu(h2 @ W1^T + bm1) -> g_mb (split bf16, K3 = 2304)
    bgemm_kernel<3 * D_, 0><<<dim3(MLP_ / 128, TOK_ / 128), 256, GSMEM_>>>(
        p_hb, p_w1b, bm1, nullptr, nullptr, p_mb, MLP_);
    // MLP2: m @ W2^T + bm2 + out1 -> d_out (fp32, K3 = 9216)
    bgemm_kernel<3 * MLP_, 1><<<dim3(D_ / 128, TOK_ / 128), 256, GSMEM_>>>(
        p_mb, p_w2b, bm2, p_out1, out, nullptr, D_);
}